// round 12
// baseline (speedup 1.0000x reference)
#include <cuda_runtime.h>

#define SC   25     // (LMAX+1)^2
#define RBC  12
#define RAC  11
#define DC   64
#define NP   15     // (l, m>=0) pairs
#define NQ   10     // m>0 pairs
#define TPB  64     // one row per thread, 64 rows per CTA

typedef unsigned long long u64;

// ---------- packed f32x2 helpers ----------
__device__ __forceinline__ u64 pk(float lo, float hi) {
    u64 r; asm("mov.b64 %0, {%1,%2};" : "=l"(r) : "f"(lo), "f"(hi)); return r;
}
__device__ __forceinline__ void unpk(u64 v, float& lo, float& hi) {
    asm("mov.b64 {%0,%1}, %2;" : "=f"(lo), "=f"(hi) : "l"(v));
}
__device__ __forceinline__ u64 fma2(u64 a, u64 b, u64 c) {
    u64 d; asm("fma.rn.f32x2 %0, %1, %2, %3;" : "=l"(d) : "l"(a), "l"(b), "l"(c)); return d;
}

// full (l,m) pair tables, p = l(l+1)/2 + m (for acc/output stages)
static __device__ const int c_ip[NP] = {0, 2,3, 6,7,8, 12,13,14,15, 20,21,22,23,24};
static __device__ const int c_in[NP] = {0, 2,1, 6,5,4, 12,11,10, 9, 20,19,18,17,16};
static __device__ const int c_m [NP] = {0, 0,1, 0,1,2,  0, 1, 2, 3,  0, 1, 2, 3, 4};

// m=0 subset: s index = l*l+l, l=0..4
static __device__ const int s0_s[5] = {0, 2, 6, 12, 20};
// m>0 subset q=0..9: (l,m) = (1,1),(2,1),(2,2),(3,1),(3,2),(3,3),(4,1),(4,2),(4,3),(4,4)
static __device__ const int q_m [NQ] = {1, 1,2, 1,2,3, 1,2,3,4};
static __device__ const int q_ip[NQ] = {3, 7,8, 13,14,15, 21,22,23,24};
static __device__ const int q_in[NQ] = {1, 5,4, 11,10, 9, 19,18,17,16};

__global__ void __launch_bounds__(TPB, 7)
gtp_main(const float* __restrict__ x1, const float* __restrict__ x2,
         const float* __restrict__ W1, const float* __restrict__ W2,
         const float* __restrict__ Y,  const float* __restrict__ Yw,
         float* __restrict__ out, int nrows)
{
    __shared__ __align__(16) u64 sW0[DC * 8];          // m=0: (W1[d,s], W2[d,s]); 4KB
    __shared__ __align__(16) ulonglong2 sWpm[DC * NQ]; // m>0: {W1(+m,-m), W2(+m,-m)}; 10KB
    __shared__ __align__(16) float4 sBuf[512];         // staging: 64 rows x 16 floats x 2 inputs; 8KB
    __shared__ __align__(16) u64 sP0 [RBC * 8];        // m=0: (P,P) per l
    __shared__ __align__(16) u64 sPpm[RBC * 16];       // m>0: (P,P) per q (+pad)
    __shared__ __align__(16) u64 sPw [RBC * 16];       // full 15: (P*qw, P*qw) (+pad)
    __shared__ __align__(16) u64 sAng[6 * 6];          // alpha half-grid j=0..5: m=0..4 pairs + pad

    const int tid = threadIdx.x;
    const float SQ2  = 1.41421356237309505f;
    const float ISQ2 = 0.70710678118654752f;

    // ---- build tables from W / Y / Yw (exact extraction, no trig) ----
    for (int t = tid; t < DC * 8; t += TPB) {
        int d = t / 8, k = t % 8;
        sW0[t] = (k < 5) ? pk(W1[d * SC + s0_s[k]], W2[d * SC + s0_s[k]]) : 0ull;
    }
    for (int t = tid; t < DC * NQ; t += TPB) {
        int d = t / NQ, q = t % NQ;
        ulonglong2 w;
        w.x = pk(W1[d * SC + q_ip[q]], W1[d * SC + q_in[q]]);
        w.y = pk(W2[d * SC + q_ip[q]], W2[d * SC + q_in[q]]);
        sWpm[t] = w;
    }

    for (int t = tid; t < RBC * 8; t += TPB) {
        int b = t / 8, l = t % 8;
        sP0[t] = (l < 5) ? pk(Y[(b * RAC) * SC + l * l + l], Y[(b * RAC) * SC + l * l + l]) : 0ull;
    }
    for (int t = tid; t < RBC * 16; t += TPB) {
        int b = t / 16, q = t % 16;
        if (q >= NQ) { sPpm[t] = 0ull; }
        else {
            float P = Y[(b * RAC) * SC + q_ip[q]] * ISQ2;   // a=0: ang = sqrt2 for m>0
            sPpm[t] = pk(P, P);
        }
    }
    for (int t = tid; t < RBC * 16; t += TPB) {
        int b = t / 16, p = t % 16;
        if (p == 15) { sPw[t] = 0ull; }
        else {
            int m = c_m[p], ip = c_ip[p];
            float y0 = Y[(b * RAC) * SC + ip];
            float P  = (m > 0) ? y0 * ISQ2 : y0;
            float qw = Yw[(b * RAC) * SC] / Y[(b * RAC) * SC]; // Y[b,0,0] > 0, const over a
            sPw[t] = pk(P * qw, P * qw);
        }
    }

    // alpha half-grid: j=0..5 (points a=6..10 are mirrors of a=5..1)
    for (int t = tid; t < 6 * 6; t += TPB) {
        int a = t / 6, m = t % 6;
        if (m == 5)      sAng[t] = 0ull;
        else if (m == 0) sAng[t] = pk(1.0f, 0.0f);
        else {
            const int b0 = RBC / 2;                            // mid Gauss node, P[m,m] != 0
            int ip = m * m + 2 * m, in_ = m * m;
            float den = Y[(b0 * RAC) * SC + ip];               // sqrt2 * P[m,m](x_b0)
            float ac2 = SQ2 * Y[(b0 * RAC + a) * SC + ip ] / den;
            float as2 = SQ2 * Y[(b0 * RAC + a) * SC + in_] / den;
            sAng[t] = pk(ac2, as2);
        }
    }

    // ---- projection: staged coalesced loads, mixed packing ----
    u64 cc0[5];                  // (c1[s], c2[s]) for m=0 s-values
    u64 c1p[NQ], c2p[NQ];        // (+m,-m) per input for m>0 pairs
    #pragma unroll
    for (int k = 0; k < 5; k++) cc0[k] = 0ull;
    #pragma unroll
    for (int q = 0; q < NQ; q++) { c1p[q] = 0ull; c2p[q] = 0ull; }

    const long long rowsLeft = (long long)nrows - (long long)blockIdx.x * TPB;
    const long long base = (long long)blockIdx.x * TPB * DC;

    #pragma unroll 1
    for (int qq = 0; qq < 4; qq++) {
        __syncthreads();
        // coalesced: 64 rows x 16 floats per input for this d-quarter
        #pragma unroll
        for (int i = 0; i < 4; i++) {
            int k = i * TPB + tid;            // 0..255
            int row = k >> 2, c4 = k & 3;
            long long rg = (row < rowsLeft) ? row : (rowsLeft - 1);
            long long g = base + rg * DC + qq * 16 + c4 * 4;
            int idx = c4 * 64 + ((row + 2 * c4) & 63);   // swizzle: conflict-free STS/LDS
            sBuf[idx]       = *(const float4*)(x1 + g);
            sBuf[256 + idx] = *(const float4*)(x2 + g);
        }
        __syncthreads();
        #pragma unroll
        for (int j = 0; j < 4; j++) {
            int idx = j * 64 + ((tid + 2 * j) & 63);
            float4 A = sBuf[idx];
            float4 B = sBuf[256 + idx];
            float av[4] = {A.x, A.y, A.z, A.w};
            float bv[4] = {B.x, B.y, B.z, B.w};
            #pragma unroll
            for (int w = 0; w < 4; w++) {
                int d = qq * 16 + j * 4 + w;
                u64 xd1  = pk(av[w], av[w]);
                u64 xd2  = pk(bv[w], bv[w]);
                u64 xd12 = pk(av[w], bv[w]);
                const u64* W0 = &sW0[d * 8];
                #pragma unroll
                for (int k = 0; k < 5; k++)
                    cc0[k] = fma2(xd12, W0[k], cc0[k]);
                const ulonglong2* Wq = &sWpm[d * NQ];
                #pragma unroll
                for (int q = 0; q < NQ; q++) {
                    ulonglong2 W = Wq[q];
                    c1p[q] = fma2(xd1, W.x, c1p[q]);
                    c2p[q] = fma2(xd2, W.y, c2p[q]);
                }
            }
        }
    }

    // ---- sphere: per beta node, F -> mirrored alpha grid -> H -> back-project ----
    u64 accp[NP];
    #pragma unroll
    for (int p = 0; p < NP; p++) accp[p] = 0ull;

    #pragma unroll 1
    for (int b = 0; b < RBC; b++) {
        const u64* P0v = &sP0[b * 8];
        const ulonglong2* Pqv = (const ulonglong2*)&sPpm[b * 16];
        const ulonglong2* Pwv = (const ulonglong2*)&sPw [b * 16];

        // m=0: F0 = (F1_0, F2_0) = sum_l cc0[l] * P[l,0]
        u64 F0 = 0ull;
        #pragma unroll
        for (int l = 0; l < 5; l++) F0 = fma2(cc0[l], P0v[l], F0);
        float f1, f2; unpk(F0, f1, f2);
        u64 g1_0 = pk(f1, 0.0f), g2_0 = pk(f2, 0.0f);

        // m>0: F1[m-1], F2[m-1] with (+m,-m) lanes
        u64 F1[4], F2[4];
        #pragma unroll
        for (int m = 0; m < 4; m++) { F1[m] = 0ull; F2[m] = 0ull; }
        #pragma unroll
        for (int qq2 = 0; qq2 < 5; qq2++) {
            ulonglong2 P2 = Pqv[qq2];
            const int q0 = 2 * qq2, q1 = 2 * qq2 + 1;
            F1[q_m[q0] - 1] = fma2(c1p[q0], P2.x, F1[q_m[q0] - 1]);
            F2[q_m[q0] - 1] = fma2(c2p[q0], P2.x, F2[q_m[q0] - 1]);
            F1[q_m[q1] - 1] = fma2(c1p[q1], P2.y, F1[q_m[q1] - 1]);
            F2[q_m[q1] - 1] = fma2(c2p[q1], P2.y, F2[q_m[q1] - 1]);
        }

        u64 H[5];
        #pragma unroll
        for (int m = 0; m < 5; m++) H[m] = 0ull;

        // alpha half-grid: chain lanes = (cos-part, sin-part); g(a)=lo+hi, g(11-a)=lo-hi
        #pragma unroll
        for (int j = 0; j < 6; j++) {
            const ulonglong2* Av = (const ulonglong2*)&sAng[j * 6];
            ulonglong2 A0 = Av[0], A1 = Av[1], A2 = Av[2];
            u64 am0 = A0.x, am1 = A0.y, am2 = A1.x, am3 = A1.y, am4 = A2.x;

            u64 g1 = g1_0, g2 = g2_0;               // m=0 seed (loop-invariant)
            g1 = fma2(F1[0], am1, g1);  g2 = fma2(F2[0], am1, g2);
            g1 = fma2(F1[1], am2, g1);  g2 = fma2(F2[1], am2, g2);
            g1 = fma2(F1[2], am3, g1);  g2 = fma2(F2[2], am3, g2);
            g1 = fma2(F1[3], am4, g1);  g2 = fma2(F2[3], am4, g2);

            float l1, h1, l2, h2;
            unpk(g1, l1, h1); unpk(g2, l2, h2);

            u64 hp;
            if (j == 0) {
                float ha = (l1 + h1) * (l2 + h2);          // a = 0 (self-mirror; sin lane = 0)
                hp = pk(ha, ha);
            } else {
                float ha = (l1 + h1) * (l2 + h2);          // point a = j
                float hb = (l1 - h1) * (l2 - h2);          // point a = 11 - j
                hp = pk(ha + hb, ha - hb);                 // (sum -> cos lane, diff -> sin lane)
            }
            H[0] = fma2(hp, am0, H[0]);
            H[1] = fma2(hp, am1, H[1]);
            H[2] = fma2(hp, am2, H[2]);
            H[3] = fma2(hp, am3, H[3]);
            H[4] = fma2(hp, am4, H[4]);
        }

        #pragma unroll
        for (int pp = 0; pp < 8; pp++) {
            ulonglong2 Pw2 = Pwv[pp];
            const int p0 = 2 * pp, p1 = 2 * pp + 1;
            accp[p0] = fma2(H[c_m[p0]], Pw2.x, accp[p0]);
            if (p1 < NP) accp[p1] = fma2(H[c_m[p1]], Pw2.y, accp[p1]);
        }
    }

    // ---- output: stage in shared (reuse sBuf + sW0 region), coalesced stores ----
    __syncthreads();                      // staging fully consumed CTA-wide
    float* sOut = (float*)sBuf;           // 8KB >= 64*25*4 = 6.4KB
    #pragma unroll
    for (int p = 0; p < NP; p++) {
        float lo, hi; unpk(accp[p], lo, hi);
        sOut[tid * SC + c_ip[p]] = lo;
        if (c_m[p] > 0) sOut[tid * SC + c_in[p]] = hi;
    }
    __syncthreads();
    const float4* sOv = (const float4*)sOut;
    const long long obase4 = (long long)blockIdx.x * TPB * SC / 4;   // CTA tile: 400 float4
    const long long otot4  = (long long)nrows * SC / 4;
    float4* og = (float4*)out;
    #pragma unroll
    for (int k = tid; k < TPB * SC / 4; k += TPB) {
        if (obase4 + k < otot4) og[obase4 + k] = sOv[k];
    }
}

extern "C" void kernel_launch(void* const* d_in, const int* in_sizes, int n_in,
                              void* d_out, int out_size) {
    const float* x1 = (const float*)d_in[0];
    const float* x2 = (const float*)d_in[1];
    const float* W1 = (const float*)d_in[2];
    const float* W2 = (const float*)d_in[3];
    const float* Y  = (const float*)d_in[4];
    const float* Yw = (const float*)d_in[5];
    float* out = (float*)d_out;

    const int nrows = in_sizes[0] / DC;            // 131072
    const int grid  = (nrows + TPB - 1) / TPB;     // 2048

    gtp_main<<<grid, TPB>>>(x1, x2, W1, W2, Y, Yw, out, nrows);
}

// round 13
// speedup vs baseline: 1.4785x; 1.4785x over previous
#include <cuda_runtime.h>

#define SC   25     // (LMAX+1)^2
#define RBC  12
#define RAC  11
#define DC   64
#define NP   15     // (l, m>=0) pairs
#define NQ   10     // m>0 pairs
#define TPB  128
#define RPC  256    // rows per CTA (2 per thread: tid and tid+128)

typedef unsigned long long u64;

// ---------- packed f32x2 helpers ----------
__device__ __forceinline__ u64 pk(float lo, float hi) {
    u64 r; asm("mov.b64 %0, {%1,%2};" : "=l"(r) : "f"(lo), "f"(hi)); return r;
}
__device__ __forceinline__ void unpk(u64 v, float& lo, float& hi) {
    asm("mov.b64 {%0,%1}, %2;" : "=f"(lo), "=f"(hi) : "l"(v));
}
__device__ __forceinline__ u64 fma2(u64 a, u64 b, u64 c) {
    u64 d; asm("fma.rn.f32x2 %0, %1, %2, %3;" : "=l"(d) : "l"(a), "l"(b), "l"(c)); return d;
}

// full (l,m) pair tables, p = l(l+1)/2 + m
static __device__ const int c_ip[NP] = {0, 2,3, 6,7,8, 12,13,14,15, 20,21,22,23,24};
static __device__ const int c_in[NP] = {0, 2,1, 6,5,4, 12,11,10, 9, 20,19,18,17,16};
static __device__ const int c_m [NP] = {0, 0,1, 0,1,2,  0, 1, 2, 3,  0, 1, 2, 3, 4};

// m=0 subset: s = l*l+l
static __device__ const int s0_s[5] = {0, 2, 6, 12, 20};
// m>0 subset q=0..9
static __device__ const int q_m [NQ] = {1, 1,2, 1,2,3, 1,2,3,4};
static __device__ const int q_ip[NQ] = {3, 7,8, 13,14,15, 21,22,23,24};
static __device__ const int q_in[NQ] = {1, 5,4, 11,10, 9, 19,18,17,16};

__global__ void __launch_bounds__(TPB, 2)
gtp_main(const float* __restrict__ x1, const float* __restrict__ x2,
         const float* __restrict__ W1, const float* __restrict__ W2,
         const float* __restrict__ Y,  const float* __restrict__ Yw,
         float* __restrict__ out, int nrows)
{
    __shared__ __align__(16) u64 sW0[DC * 8];          // m=0 (c1,c2)-pack weights; 4KB
    __shared__ __align__(16) ulonglong2 sWpm[DC * NQ]; // m>0 {W1(+m,-m), W2(+m,-m)}; 10KB
    __shared__ __align__(16) float4 sBuf[1024];        // chunk staging 256r x 2f4 x 2in; 16KB
    __shared__ __align__(16) u64 sP0 [RBC * 8];
    __shared__ __align__(16) u64 sPpm[RBC * 16];
    __shared__ __align__(16) u64 sPw [RBC * 16];
    __shared__ __align__(16) u64 sAng[6 * 6];

    const int tid = threadIdx.x;
    const float SQ2  = 1.41421356237309505f;
    const float ISQ2 = 0.70710678118654752f;

    // ---- build tables from W / Y / Yw (exact extraction, no trig) ----
    for (int t = tid; t < DC * 8; t += TPB) {
        int d = t / 8, k = t % 8;
        sW0[t] = (k < 5) ? pk(W1[d * SC + s0_s[k]], W2[d * SC + s0_s[k]]) : 0ull;
    }
    for (int t = tid; t < DC * NQ; t += TPB) {
        int d = t / NQ, q = t % NQ;
        ulonglong2 w;
        w.x = pk(W1[d * SC + q_ip[q]], W1[d * SC + q_in[q]]);
        w.y = pk(W2[d * SC + q_ip[q]], W2[d * SC + q_in[q]]);
        sWpm[t] = w;
    }
    for (int t = tid; t < RBC * 8; t += TPB) {
        int b = t / 8, l = t % 8;
        sP0[t] = (l < 5) ? pk(Y[(b * RAC) * SC + l * l + l], Y[(b * RAC) * SC + l * l + l]) : 0ull;
    }
    for (int t = tid; t < RBC * 16; t += TPB) {
        int b = t / 16, q = t % 16;
        if (q >= NQ) { sPpm[t] = 0ull; }
        else {
            float P = Y[(b * RAC) * SC + q_ip[q]] * ISQ2;   // a=0: ang = sqrt2 for m>0
            sPpm[t] = pk(P, P);
        }
    }
    for (int t = tid; t < RBC * 16; t += TPB) {
        int b = t / 16, p = t % 16;
        if (p == 15) { sPw[t] = 0ull; }
        else {
            int m = c_m[p], ip = c_ip[p];
            float y0 = Y[(b * RAC) * SC + ip];
            float P  = (m > 0) ? y0 * ISQ2 : y0;
            float qw = Yw[(b * RAC) * SC] / Y[(b * RAC) * SC]; // Y[b,0,0] > 0, const over a
            sPw[t] = pk(P * qw, P * qw);
        }
    }
    for (int t = tid; t < 6 * 6; t += TPB) {        // alpha half-grid (a=6..10 mirror a=5..1)
        int a = t / 6, m = t % 6;
        if (m == 5)      sAng[t] = 0ull;
        else if (m == 0) sAng[t] = pk(1.0f, 0.0f);
        else {
            const int b0 = RBC / 2;
            int ip = m * m + 2 * m, in_ = m * m;
            float den = Y[(b0 * RAC) * SC + ip];    // sqrt2 * P[m,m](x_b0)
            float ac2 = SQ2 * Y[(b0 * RAC + a) * SC + ip ] / den;
            float as2 = SQ2 * Y[(b0 * RAC + a) * SC + in_] / den;
            sAng[t] = pk(ac2, as2);
        }
    }

    // ================= projection: 2 rows (tid, tid+128), mixed packing ============
    u64 cc0[2][5], c1p[2][NQ], c2p[2][NQ];
    #pragma unroll
    for (int r = 0; r < 2; r++) {
        #pragma unroll
        for (int k = 0; k < 5; k++) cc0[r][k] = 0ull;
        #pragma unroll
        for (int q = 0; q < NQ; q++) { c1p[r][q] = 0ull; c2p[r][q] = 0ull; }
    }

    const long long rowsLeft = (long long)nrows - (long long)blockIdx.x * RPC;
    const long long base = (long long)blockIdx.x * RPC * DC;

    #pragma unroll 1
    for (int c = 0; c < 8; c++) {       // 8-float d-chunks
        __syncthreads();
        // stage: 256 rows x 2 float4 per input
        #pragma unroll
        for (int i = 0; i < 4; i++) {
            int k = i * TPB + tid;        // 0..511
            int row = k >> 1, c4 = k & 1;
            long long rg = (row < rowsLeft) ? row : (rowsLeft - 1);
            long long g = base + rg * DC + c * 8 + c4 * 4;
            int idx = c4 * 256 + ((row + 2 * c4) & 255);
            sBuf[idx]       = *(const float4*)(x1 + g);
            sBuf[512 + idx] = *(const float4*)(x2 + g);
        }
        __syncthreads();
        // consume both rows
        #pragma unroll
        for (int j = 0; j < 2; j++) {
            int iA = j * 256 + ((tid + 2 * j) & 255);          // row = tid
            int iB = j * 256 + ((tid + 128 + 2 * j) & 255);    // row = tid+128
            float4 Xa[2] = { sBuf[iA],       sBuf[iB]       };
            float4 Xb[2] = { sBuf[512 + iA], sBuf[512 + iB] };
            #pragma unroll
            for (int r = 0; r < 2; r++) {
                float av[4] = {Xa[r].x, Xa[r].y, Xa[r].z, Xa[r].w};
                float bv[4] = {Xb[r].x, Xb[r].y, Xb[r].z, Xb[r].w};
                #pragma unroll
                for (int w = 0; w < 4; w++) {
                    int d = c * 8 + j * 4 + w;
                    u64 xd1  = pk(av[w], av[w]);
                    u64 xd2  = pk(bv[w], bv[w]);
                    u64 xd12 = pk(av[w], bv[w]);
                    const u64* W0 = &sW0[d * 8];
                    #pragma unroll
                    for (int k = 0; k < 5; k++)
                        cc0[r][k] = fma2(xd12, W0[k], cc0[r][k]);
                    const ulonglong2* Wq = &sWpm[d * NQ];
                    #pragma unroll
                    for (int q = 0; q < NQ; q++) {
                        ulonglong2 W = Wq[q];
                        c1p[r][q] = fma2(xd1, W.x, c1p[r][q]);
                        c2p[r][q] = fma2(xd2, W.y, c2p[r][q]);
                    }
                }
            }
        }
    }

    // ================= sphere: both rows interleaved per beta node =================
    u64 accp[2][NP];
    #pragma unroll
    for (int r = 0; r < 2; r++)
        #pragma unroll
        for (int p = 0; p < NP; p++) accp[r][p] = 0ull;

    #pragma unroll 1
    for (int b = 0; b < RBC; b++) {
        const u64* P0v = &sP0[b * 8];
        const ulonglong2* Pqv = (const ulonglong2*)&sPpm[b * 16];
        const ulonglong2* Pwv = (const ulonglong2*)&sPw [b * 16];

        u64 g1_0[2], g2_0[2];
        u64 F1[2][4], F2[2][4];
        #pragma unroll
        for (int r = 0; r < 2; r++) {
            u64 F0 = 0ull;
            #pragma unroll
            for (int l = 0; l < 5; l++) F0 = fma2(cc0[r][l], P0v[l], F0);
            float f1, f2; unpk(F0, f1, f2);
            g1_0[r] = pk(f1, 0.0f); g2_0[r] = pk(f2, 0.0f);

            #pragma unroll
            for (int m = 0; m < 4; m++) { F1[r][m] = 0ull; F2[r][m] = 0ull; }
            #pragma unroll
            for (int qq = 0; qq < 5; qq++) {
                ulonglong2 P2 = Pqv[qq];
                const int q0 = 2 * qq, q1 = 2 * qq + 1;
                F1[r][q_m[q0] - 1] = fma2(c1p[r][q0], P2.x, F1[r][q_m[q0] - 1]);
                F2[r][q_m[q0] - 1] = fma2(c2p[r][q0], P2.x, F2[r][q_m[q0] - 1]);
                F1[r][q_m[q1] - 1] = fma2(c1p[r][q1], P2.y, F1[r][q_m[q1] - 1]);
                F2[r][q_m[q1] - 1] = fma2(c2p[r][q1], P2.y, F2[r][q_m[q1] - 1]);
            }
        }

        u64 H[2][5];
        #pragma unroll
        for (int r = 0; r < 2; r++)
            #pragma unroll
            for (int m = 0; m < 5; m++) H[r][m] = 0ull;

        #pragma unroll
        for (int j = 0; j < 6; j++) {
            const ulonglong2* Av = (const ulonglong2*)&sAng[j * 6];
            ulonglong2 A0 = Av[0], A1 = Av[1], A2 = Av[2];
            u64 am0 = A0.x, am1 = A0.y, am2 = A1.x, am3 = A1.y, am4 = A2.x;

            #pragma unroll
            for (int r = 0; r < 2; r++) {
                u64 g1 = g1_0[r], g2 = g2_0[r];
                g1 = fma2(F1[r][0], am1, g1);  g2 = fma2(F2[r][0], am1, g2);
                g1 = fma2(F1[r][1], am2, g1);  g2 = fma2(F2[r][1], am2, g2);
                g1 = fma2(F1[r][2], am3, g1);  g2 = fma2(F2[r][2], am3, g2);
                g1 = fma2(F1[r][3], am4, g1);  g2 = fma2(F2[r][3], am4, g2);

                float l1, h1, l2, h2;
                unpk(g1, l1, h1); unpk(g2, l2, h2);

                u64 hp;
                if (j == 0) {
                    float ha = (l1 + h1) * (l2 + h2);      // a = 0 (self-mirror)
                    hp = pk(ha, ha);
                } else {
                    float ha = (l1 + h1) * (l2 + h2);      // a = j
                    float hb = (l1 - h1) * (l2 - h2);      // a = 11 - j
                    hp = pk(ha + hb, ha - hb);
                }
                H[r][0] = fma2(hp, am0, H[r][0]);
                H[r][1] = fma2(hp, am1, H[r][1]);
                H[r][2] = fma2(hp, am2, H[r][2]);
                H[r][3] = fma2(hp, am3, H[r][3]);
                H[r][4] = fma2(hp, am4, H[r][4]);
            }
        }

        #pragma unroll
        for (int r = 0; r < 2; r++)
            #pragma unroll
            for (int pp = 0; pp < 8; pp++) {
                ulonglong2 Pw2 = Pwv[pp];
                const int p0 = 2 * pp, p1 = 2 * pp + 1;
                accp[r][p0] = fma2(H[r][c_m[p0]], Pw2.x, accp[r][p0]);
                if (p1 < NP) accp[r][p1] = fma2(H[r][c_m[p1]], Pw2.y, accp[r][p1]);
            }
    }

    // ================= output: two 128-row passes through shared staging ==========
    float* sOut = (float*)sBuf;                      // 12.8KB per pass
    const long long otot4 = (long long)nrows * SC / 4;
    float4* og = (float4*)out;
    #pragma unroll 1
    for (int r = 0; r < 2; r++) {
        __syncthreads();                             // staging / previous pass fully consumed
        #pragma unroll
        for (int p = 0; p < NP; p++) {
            float lo, hi; unpk(accp[r][p], lo, hi);
            sOut[tid * SC + c_ip[p]] = lo;
            if (c_m[p] > 0) sOut[tid * SC + c_in[p]] = hi;
        }
        __syncthreads();
        const float4* sOv = (const float4*)sOut;
        const long long obase4 = ((long long)blockIdx.x * RPC + r * TPB) * SC / 4;
        #pragma unroll
        for (int k = tid; k < TPB * SC / 4; k += TPB) {
            if (obase4 + k < otot4) og[obase4 + k] = sOv[k];
        }
    }
}

extern "C" void kernel_launch(void* const* d_in, const int* in_sizes, int n_in,
                              void* d_out, int out_size) {
    const float* x1 = (const float*)d_in[0];
    const float* x2 = (const float*)d_in[1];
    const float* W1 = (const float*)d_in[2];
    const float* W2 = (const float*)d_in[3];
    const float* Y  = (const float*)d_in[4];
    const float* Yw = (const float*)d_in[5];
    float* out = (float*)d_out;

    const int nrows = in_sizes[0] / DC;            // 131072
    const int grid  = (nrows + RPC - 1) / RPC;     // 512

    gtp_main<<<grid, TPB>>>(x1, x2, W1, W2, Y, Yw, out, nrows);
}